// round 17
// baseline (speedup 1.0000x reference)
#include <cuda_runtime.h>
#include <cuda_bf16.h>
#include <math.h>
#include <stdint.h>

#define D_MODEL 1024
#define NHEADS  16
#define HDIM    64
#define BATCH   2
#define SEQ     2048
#define MTOT    (BATCH*SEQ)
#define NELEM_X (MTOT*D_MODEL)      // 4194304
#define NELEM_W (D_MODEL*D_MODEL)   // 1048576
#define QSCALE  11.5415603f         // 8 * log2(e): softmax done in base-2

// ---------------- scratch (device globals: no allocation allowed) ----------------
__device__ __nv_bfloat16 g_xqh[NELEM_X], g_xql[NELEM_X];
__device__ __nv_bfloat16 g_xkh[NELEM_X], g_xkl[NELEM_X];
__device__ __nv_bfloat16 g_xvh[NELEM_X], g_xvl[NELEM_X];
__device__ __nv_bfloat16 g_wqh[NELEM_W], g_wql[NELEM_W];
__device__ __nv_bfloat16 g_wkh[NELEM_W], g_wkl[NELEM_W];
__device__ __nv_bfloat16 g_wvh[NELEM_W], g_wvl[NELEM_W];
__device__ __nv_bfloat16 g_woh[NELEM_W], g_wol[NELEM_W];
__device__ __nv_bfloat16 g_qh[NELEM_X],  g_ql[NELEM_X];   // [B,H,S,Hd], pre-scaled x 8*log2e
__device__ __nv_bfloat16 g_kh[NELEM_X],  g_kl[NELEM_X];   // [B,H,S,Hd]
__device__ __nv_bfloat16 g_vh[NELEM_X],  g_vl[NELEM_X];   // [B,H,S,Hd]
__device__ __nv_bfloat16 g_ah[NELEM_X],  g_al[NELEM_X];   // [B,S,D]

// 2-term bf16 split: x ~= hi + lo, |err| ~ 2^-17 |x|
__device__ __forceinline__ void split2(float x, __nv_bfloat16& h, __nv_bfloat16& l) {
    h = __float2bfloat16(x);
    l = __float2bfloat16(x - __bfloat162float(h));
}

__device__ __forceinline__ float ex2(float x) {   // raw EX2 (no pre-mul)
    float r; asm("ex2.approx.f32 %0, %1;" : "=f"(r) : "f"(x)); return r;
}

__device__ __forceinline__ uint32_t smem_u32(const void* p) {
    uint32_t a;
    asm("{ .reg .u64 t; cvta.to.shared.u64 t, %1; cvt.u32.u64 %0, t; }" : "=r"(a) : "l"(p));
    return a;
}
__device__ __forceinline__ void cp16(uint32_t dst, const void* src) {
    asm volatile("cp.async.cg.shared.global [%0], [%1], 16;" :: "r"(dst), "l"(src));
}
#define CP_COMMIT() asm volatile("cp.async.commit_group;" ::: "memory")
#define CP_WAIT0()  asm volatile("cp.async.wait_group 0;" ::: "memory")

// ---- raw mma.sync helpers (defined layouts, portable PTX) ----
__device__ __forceinline__ void ldsm4(uint32_t* d, uint32_t a) {
    asm volatile("ldmatrix.sync.aligned.m8n8.x4.shared.b16 {%0,%1,%2,%3}, [%4];"
        : "=r"(d[0]), "=r"(d[1]), "=r"(d[2]), "=r"(d[3]) : "r"(a));
}
__device__ __forceinline__ void ldsm4t(uint32_t* d, uint32_t a) {
    asm volatile("ldmatrix.sync.aligned.m8n8.x4.trans.shared.b16 {%0,%1,%2,%3}, [%4];"
        : "=r"(d[0]), "=r"(d[1]), "=r"(d[2]), "=r"(d[3]) : "r"(a));
}
__device__ __forceinline__ void mma16816(float* c, const uint32_t* a, const uint32_t* b) {
    asm volatile("mma.sync.aligned.m16n8k16.row.col.f32.bf16.bf16.f32 "
        "{%0,%1,%2,%3}, {%4,%5,%6,%7}, {%8,%9}, {%0,%1,%2,%3};"
        : "+f"(c[0]), "+f"(c[1]), "+f"(c[2]), "+f"(c[3])
        : "r"(a[0]), "r"(a[1]), "r"(a[2]), "r"(a[3]), "r"(b[0]), "r"(b[1]));
}
__device__ __forceinline__ uint32_t packbf(__nv_bfloat16 lo, __nv_bfloat16 hi) {
    __nv_bfloat162 t; t.x = lo; t.y = hi;
    return *reinterpret_cast<uint32_t*>(&t);
}

// =====================================================================
// fused split kernel: 7 arrays in one launch (block-range dispatch)
// =====================================================================
#define XBLK (NELEM_X/4/256)   // 4096
#define WBLK (NELEM_W/4/256)   // 1024
#define SPLIT_BLOCKS (3*XBLK + 4*WBLK)

__global__ __launch_bounds__(256) void split_all_kernel(
    const float* __restrict__ q, const float* __restrict__ k, const float* __restrict__ v,
    const float* __restrict__ wq, const float* __restrict__ wk,
    const float* __restrict__ wv, const float* __restrict__ wo)
{
    const int bid = blockIdx.x;
    const float* src; __nv_bfloat16 *h, *l; int i;
    if (bid < 3*XBLK) {
        const int which = bid / XBLK;
        i = (bid - which*XBLK) * 256 + threadIdx.x;
        src = (which == 0) ? q : (which == 1) ? k : v;
        h   = (which == 0) ? g_xqh : (which == 1) ? g_xkh : g_xvh;
        l   = (which == 0) ? g_xql : (which == 1) ? g_xkl : g_xvl;
    } else {
        const int wb = bid - 3*XBLK;
        const int which = wb / WBLK;
        i = (wb - which*WBLK) * 256 + threadIdx.x;
        src = (which == 0) ? wq : (which == 1) ? wk : (which == 2) ? wv : wo;
        h   = (which == 0) ? g_wqh : (which == 1) ? g_wkh : (which == 2) ? g_wvh : g_woh;
        l   = (which == 0) ? g_wql : (which == 1) ? g_wkl : (which == 2) ? g_wvl : g_wol;
    }
    float4 val = reinterpret_cast<const float4*>(src)[i];
    __nv_bfloat16 h0,h1,h2,h3,l0,l1,l2,l3;
    split2(val.x,h0,l0); split2(val.y,h1,l1); split2(val.z,h2,l2); split2(val.w,h3,l3);
    __nv_bfloat162 t;
    __nv_bfloat162* H = reinterpret_cast<__nv_bfloat162*>(h) + (size_t)i*2;
    __nv_bfloat162* L = reinterpret_cast<__nv_bfloat162*>(l) + (size_t)i*2;
    t.x=h0; t.y=h1; H[0]=t;  t.x=h2; t.y=h3; H[1]=t;
    t.x=l0; t.y=l1; L[0]=t;  t.x=l2; t.y=l3; L[1]=t;
}

// =====================================================================
// bf16 GEMM via raw mma.sync: C = (Xh+Xl)(Wh+Wl)^T + bias (3-pass)
// BM=BN=128, BK=32, 8 warps (4m x 2n), warp tile 32x64.
// Single barrier per stage; B-fragment ldsm software-pipelined across np.
// =====================================================================
#define SPB 80                     // stage row pitch bytes (32 bf16 data + pad)
#define MAT_BYTES (128*SPB)        // 10240
#define STAGE_BYTES (4*MAT_BYTES)  // 40960 (Ah,Al,Bh,Bl)
#define GEMM_SMEM (2*STAGE_BYTES)  // 81920

// OUT_MODE: 0 = split-heads bf16 hi/lo pair,  1 = f32 row-major
template<int OUT_MODE>
__device__ __forceinline__ void gemm_mma_body(
    const __nv_bfloat16* __restrict__ Xh, const __nv_bfloat16* __restrict__ Xl,
    const __nv_bfloat16* __restrict__ Wh, const __nv_bfloat16* __restrict__ Wl,
    const float* __restrict__ bias,
    __nv_bfloat16* outH, __nv_bfloat16* outL, float* outF, float prescale)
{
    extern __shared__ __align__(128) char smem[];
    const uint32_t sb = smem_u32(smem);

    const int tid  = threadIdx.x;
    const int wid  = tid >> 5;
    const int lane = tid & 31;
    const int m0   = blockIdx.y * 128;
    const int n0   = blockIdx.x * 128;
    const int mw   = wid >> 1;       // 0..3
    const int nw   = wid & 1;        // 0..1
    const int g    = lane >> 2;      // row group 0..7
    const int t    = lane & 3;       // col pair 0..3

    float acc[2][8][4];
    #pragma unroll
    for (int mi = 0; mi < 2; mi++)
        #pragma unroll
        for (int n8 = 0; n8 < 8; n8++)
            #pragma unroll
            for (int c = 0; c < 4; c++) acc[mi][n8][c] = 0.f;

    // ldmatrix lane-address components
    const uint32_t aOff = (uint32_t)((lane & 15)*SPB + (lane >> 4)*16);
    const uint32_t bOff = (uint32_t)(((lane & 7) + ((lane >> 4) << 3))*SPB + ((lane >> 3) & 1)*16);

    auto issue = [&](int s, int b) {
        const uint32_t base = sb + (uint32_t)b * STAGE_BYTES;
        #pragma unroll
        for (int mat = 0; mat < 4; mat++) {
            const __nv_bfloat16* gsrc = (mat==0) ? Xh : (mat==1) ? Xl : (mat==2) ? Wh : Wl;
            const int rbase = (mat < 2) ? m0 : n0;
            #pragma unroll
            for (int half = 0; half < 2; half++) {
                const int chunk = half*256 + tid;       // 0..511
                const int row = chunk >> 2, col = chunk & 3;
                cp16(base + (uint32_t)mat*MAT_BYTES + row*SPB + col*16,
                     gsrc + (size_t)(rbase + row) * D_MODEL + s*32 + col*8);
            }
        }
    };

    issue(0, 0); CP_COMMIT();

    for (int s = 0; s < D_MODEL/32; s++) {
        CP_WAIT0();        // stage s landed (own thread's copies)
        __syncthreads();   // publish stage s; close iter s-1 reads (issue-safety)
        if (s < D_MODEL/32 - 1) { issue(s+1, (s+1)&1); CP_COMMIT(); }

        const uint32_t Ahb = sb + (uint32_t)(s & 1) * STAGE_BYTES;
        const uint32_t Alb = Ahb + MAT_BYTES;
        const uint32_t Bhb = Ahb + 2*MAT_BYTES;
        const uint32_t Blb = Ahb + 3*MAT_BYTES;

        #pragma unroll
        for (int kk = 0; kk < 2; kk++) {
            uint32_t ah[2][4], al[2][4];
            #pragma unroll
            for (int mi = 0; mi < 2; mi++) {
                ldsm4(ah[mi], Ahb + (uint32_t)((mw*32 + mi*16)*SPB) + kk*32 + aOff);
                ldsm4(al[mi], Alb + (uint32_t)((mw*32 + mi*16)*SPB) + kk*32 + aOff);
            }
            // software-pipelined B fragments: load np+1 before consuming np
            uint32_t bh4[2][4], bl4[2][4];
            ldsm4(bh4[0], Bhb + (uint32_t)((nw*64)*SPB) + kk*32 + bOff);
            ldsm4(bl4[0], Blb + (uint32_t)((nw*64)*SPB) + kk*32 + bOff);
            #pragma unroll
            for (int np = 0; np < 4; np++) {
                const int cur = np & 1, nxt = cur ^ 1;
                if (np < 3) {
                    ldsm4(bh4[nxt], Bhb + (uint32_t)((nw*64 + (np+1)*16)*SPB) + kk*32 + bOff);
                    ldsm4(bl4[nxt], Blb + (uint32_t)((nw*64 + (np+1)*16)*SPB) + kk*32 + bOff);
                }
                #pragma unroll
                for (int mi = 0; mi < 2; mi++) {
                    mma16816(acc[mi][2*np],   ah[mi], bh4[cur]);
                    mma16816(acc[mi][2*np],   ah[mi], bl4[cur]);
                    mma16816(acc[mi][2*np],   al[mi], bh4[cur]);
                    mma16816(acc[mi][2*np+1], ah[mi], bh4[cur]+2);
                    mma16816(acc[mi][2*np+1], ah[mi], bl4[cur]+2);
                    mma16816(acc[mi][2*np+1], al[mi], bh4[cur]+2);
                }
            }
        }
    }

    // ---- register epilogue: thread holds rows (g, g+8), cols (2t, 2t+1) per n8 ----
    #pragma unroll
    for (int mi = 0; mi < 2; mi++) {
        const int r0 = m0 + mw*32 + mi*16 + g;
        const int r1 = r0 + 8;
        #pragma unroll
        for (int n8 = 0; n8 < 8; n8++) {
            const int ncol = n0 + nw*64 + n8*8 + t*2;
            const float2 bv2 = *reinterpret_cast<const float2*>(bias + ncol);
            float c00 = acc[mi][n8][0] + bv2.x, c01 = acc[mi][n8][1] + bv2.y;
            float c10 = acc[mi][n8][2] + bv2.x, c11 = acc[mi][n8][3] + bv2.y;
            if (OUT_MODE == 0) {
                c00 *= prescale; c01 *= prescale; c10 *= prescale; c11 *= prescale;
                const int h_ = ncol >> 6, d0 = ncol & 63;
                const size_t base0 = (((size_t)((r0 >> 11)*NHEADS + h_) * SEQ + (r0 & (SEQ-1))) * HDIM) + d0;
                const size_t base1 = (((size_t)((r1 >> 11)*NHEADS + h_) * SEQ + (r1 & (SEQ-1))) * HDIM) + d0;
                __nv_bfloat16 h0,l0,h1,l1;
                split2(c00,h0,l0); split2(c01,h1,l1);
                *reinterpret_cast<uint32_t*>(outH + base0) = packbf(h0,h1);
                *reinterpret_cast<uint32_t*>(outL + base0) = packbf(l0,l1);
                split2(c10,h0,l0); split2(c11,h1,l1);
                *reinterpret_cast<uint32_t*>(outH + base1) = packbf(h0,h1);
                *reinterpret_cast<uint32_t*>(outL + base1) = packbf(l0,l1);
            } else {
                float2* d0p = reinterpret_cast<float2*>(outF + (size_t)r0 * D_MODEL + ncol);
                float2* d1p = reinterpret_cast<float2*>(outF + (size_t)r1 * D_MODEL + ncol);
                *d0p = make_float2(c00, c01);
                *d1p = make_float2(c10, c11);
            }
        }
    }
}

__global__ __launch_bounds__(256, 2) void qkv_proj_kernel(
    const float* __restrict__ bq, const float* __restrict__ bk, const float* __restrict__ bv)
{
    if (blockIdx.z == 0)
        gemm_mma_body<0>(g_xqh, g_xql, g_wqh, g_wql, bq, g_qh, g_ql, nullptr, QSCALE);
    else if (blockIdx.z == 1)
        gemm_mma_body<0>(g_xkh, g_xkl, g_wkh, g_wkl, bk, g_kh, g_kl, nullptr, 1.0f);
    else
        gemm_mma_body<0>(g_xvh, g_xvl, g_wvh, g_wvl, bv, g_vh, g_vl, nullptr, 1.0f);
}

__global__ __launch_bounds__(256, 2) void out_proj_kernel(
    const float* __restrict__ bo, float* __restrict__ out)
{
    gemm_mma_body<1>(g_ah, g_al, g_woh, g_wol, bo, nullptr, nullptr, out, 1.0f);
}

// =====================================================================
// FA2-style flash attention: raw mma.sync, register softmax (base-2),
// register O. 128 q-rows/block, 8 warps, 64-key tiles. 2-deep cp.async
// K/V ring, single barrier per tile. K/V fragment ldsm pipelined.
// =====================================================================
#define PBB 144                            // row pitch bytes (72 bf16)
#define OFF_QH 0
#define OFF_QL (128*PBB)                   // 18432
#define OFF_KV (2*128*PBB)                 // 36864
#define KV_MAT (64*PBB)                    // 9216
#define KV_STAGE (4*KV_MAT)                // 36864 (Kh,Kl,Vh,Vl)
#define ATTN_SMEM (OFF_KV + 2*KV_STAGE)    // 110592

__global__ __launch_bounds__(256, 2) void flash_attn_mma()
{
    extern __shared__ __align__(128) char smem[];
    const uint32_t sb = smem_u32(smem);

    const int tid  = threadIdx.x;
    const int wid  = tid >> 5;
    const int lane = tid & 31;
    const int q0   = blockIdx.x * 128;
    const int bh   = blockIdx.y;
    const int g    = lane >> 2;
    const int t    = lane & 3;

    {
        const int r  = tid >> 1;
        const int ch = (tid & 1) * 32;
        const uint4* shp = reinterpret_cast<const uint4*>(g_qh + ((size_t)bh*SEQ + q0 + r)*HDIM + ch);
        const uint4* slp = reinterpret_cast<const uint4*>(g_ql + ((size_t)bh*SEQ + q0 + r)*HDIM + ch);
        uint4* dh = reinterpret_cast<uint4*>(smem + OFF_QH + r*PBB + ch*2);
        uint4* dl = reinterpret_cast<uint4*>(smem + OFF_QL + r*PBB + ch*2);
        #pragma unroll
        for (int i = 0; i < 4; i++) { dh[i] = shp[i]; dl[i] = slp[i]; }
    }

    const uint32_t qAddr = sb + OFF_QH + (uint32_t)((wid*16 + (lane & 15))*PBB + (lane >> 4)*16);
    const uint32_t kOff = (uint32_t)(((lane & 7) + ((lane >> 4) << 3)) * PBB + ((lane >> 3) & 1) * 16);
    const uint32_t vOff = (uint32_t)((((lane & 7) + (((lane >> 3) & 1) << 3)) * PBB) + ((lane >> 4) & 1) * 16);

    auto issueKV = [&](int kt, int b) {
        const uint32_t base = sb + OFF_KV + (uint32_t)b * KV_STAGE;
        #pragma unroll
        for (int mat = 0; mat < 4; mat++) {
            const __nv_bfloat16* gsrc = (mat==0) ? g_kh : (mat==1) ? g_kl : (mat==2) ? g_vh : g_vl;
            #pragma unroll
            for (int half = 0; half < 2; half++) {
                const int chunk = half*256 + tid;
                const int row = chunk >> 3, col = chunk & 7;
                cp16(base + (uint32_t)mat*KV_MAT + row*PBB + col*16,
                     gsrc + (size_t)(bh*SEQ + kt*64 + row) * HDIM + col*8);
            }
        }
    };

    float o[8][4];
    #pragma unroll
    for (int ni = 0; ni < 8; ni++)
        #pragma unroll
        for (int c = 0; c < 4; c++) o[ni][c] = 0.f;
    float m0 = -1e30f, m1 = -1e30f, l0 = 0.f, l1 = 0.f;

    issueKV(0, 0); CP_COMMIT();

    for (int kt = 0; kt < SEQ/64; kt++) {
        CP_WAIT0();        // K/V stage kt landed
        __syncthreads();   // publish stage kt (and Q on kt=0); close iter kt-1 reads
        if (kt < SEQ/64 - 1) { issueKV(kt+1, (kt+1)&1); CP_COMMIT(); }

        const uint32_t Kb  = sb + OFF_KV + (uint32_t)(kt & 1) * KV_STAGE;
        const uint32_t Klb = Kb + KV_MAT;
        const uint32_t Vb  = Kb + 2*KV_MAT;
        const uint32_t Vlb = Kb + 3*KV_MAT;

        float s[8][4];
        #pragma unroll
        for (int n8 = 0; n8 < 8; n8++)
            #pragma unroll
            for (int c = 0; c < 4; c++) s[n8][c] = 0.f;

        // ---- S = Q K^T (scores already in base-2 units via Q prescale) ----
        #pragma unroll
        for (int kk = 0; kk < 4; kk++) {
            uint32_t qh[4], ql[4];
            ldsm4(qh, qAddr + kk*32);
            ldsm4(ql, qAddr + (OFF_QL - OFF_QH) + kk*32);
            uint32_t bhf[2][4], blf[2][4];
            ldsm4(bhf[0], Kb  + kk*32 + kOff);
            ldsm4(blf[0], Klb + kk*32 + kOff);
            #pragma unroll
            for (int np = 0; np < 4; np++) {
                const int cur = np & 1, nxt = cur ^ 1;
                if (np < 3) {
                    ldsm4(bhf[nxt], Kb  + (np+1)*16*PBB + kk*32 + kOff);
                    ldsm4(blf[nxt], Klb + (np+1)*16*PBB + kk*32 + kOff);
                }
                mma16816(s[2*np],   qh, bhf[cur]);     mma16816(s[2*np],   qh, blf[cur]);     mma16816(s[2*np],   ql, bhf[cur]);
                mma16816(s[2*np+1], qh, bhf[cur]+2);   mma16816(s[2*np+1], qh, blf[cur]+2);   mma16816(s[2*np+1], ql, bhf[cur]+2);
            }
        }

        // ---- register softmax, base-2 (rows g, g+8; quad shfl) ----
        float mx0 = -1e30f, mx1 = -1e30f;
        #pragma unroll
        for (int n8 = 0; n8 < 8; n8++) {
            mx0 = fmaxf(mx0, fmaxf(s[n8][0], s[n8][1]));
            mx1 = fmaxf(mx1, fmaxf(s[n8][2], s[n8][3]));
        }
        mx0 = fmaxf(mx0, __shfl_xor_sync(0xffffffffu, mx0, 1));
        mx0 = fmaxf(mx0, __shfl_xor_sync(0xffffffffu, mx0, 2));
        mx1 = fmaxf(mx1, __shfl_xor_sync(0xffffffffu, mx1, 1));
        mx1 = fmaxf(mx1, __shfl_xor_sync(0xffffffffu, mx1, 2));
        const float mn0 = fmaxf(m0, mx0), mn1 = fmaxf(m1, mx1);
        const float a0 = ex2(m0 - mn0), a1 = ex2(m1 - mn1);
        m0 = mn0; m1 = mn1;

        float sum0 = 0.f, sum1 = 0.f;
        #pragma unroll
        for (int n8 = 0; n8 < 8; n8++) {
            s[n8][0] = ex2(s[n8][0] - mn0);
            s[n8][1] = ex2(s[n8][1] - mn0);
            s[n8][2] = ex2(s[n8][2] - mn1);
            s[n8][3] = ex2(s[n8][3] - mn1);
            sum0 += s[n8][0] + s[n8][1];
            sum1 += s[n8][2] + s[n8][3];
        }
        sum0 += __shfl_xor_sync(0xffffffffu, sum0, 1);
        sum0 += __shfl_xor_sync(0xffffffffu, sum0, 2);
        sum1 += __shfl_xor_sync(0xffffffffu, sum1, 1);
        sum1 += __shfl_xor_sync(0xffffffffu, sum1, 2);
        l0 = l0*a0 + sum0;
        l1 = l1*a1 + sum1;

        #pragma unroll
        for (int ni = 0; ni < 8; ni++) {
            o[ni][0] *= a0; o[ni][1] *= a0;
            o[ni][2] *= a1; o[ni][3] *= a1;
        }

        // ---- O += P V (P from S registers; V fragment ldsm pipelined) ----
        #pragma unroll
        for (int kk = 0; kk < 4; kk++) {
            uint32_t ph[4], pl[4];
            {
                __nv_bfloat16 h00,l00,h01,l01,h02,l02,h03,l03;
                __nv_bfloat16 h10,l10,h11,l11,h12,l12,h13,l13;
                split2(s[2*kk][0],   h00, l00); split2(s[2*kk][1],   h01, l01);
                split2(s[2*kk][2],   h02, l02); split2(s[2*kk][3],   h03, l03);
                split2(s[2*kk+1][0], h10, l10); split2(s[2*kk+1][1], h11, l11);
                split2(s[2*kk+1][2], h12, l12); split2(s[2*kk+1][3], h13, l13);
                ph[0] = packbf(h00, h01); pl[0] = packbf(l00, l01);
                ph[1] = packbf(h02, h03); pl[1] = packbf(l02, l03);
                ph[2] = packbf(h10, h11); pl[2] = packbf(l10, l11);
                ph[3] = packbf(h12, h13); pl[3] = packbf(l12, l13);
            }
            uint32_t vh[2][4], vl[2][4];
            ldsm4t(vh[0], Vb  + kk*16*PBB + vOff);
            ldsm4t(vl[0], Vlb + kk*16*PBB + vOff);
            #pragma unroll
            for (int np = 0; np < 4; np++) {
                const int cur = np & 1, nxt = cur ^ 1;
                if (np < 3) {
                    ldsm4t(vh[nxt], Vb  + kk*16*PBB + (np+1)*32 + vOff);
                    ldsm4t(vl[nxt], Vlb + kk*16*PBB + (np+1)*32 + vOff);
                }
                mma16816(o[2*np],   ph, vh[cur]);     mma16816(o[2*np],   ph, vl[cur]);     mma16816(o[2*np],   pl, vh[cur]);
                mma16816(o[2*np+1], ph, vh[cur]+2);   mma16816(o[2*np+1], ph, vl[cur]+2);   mma16816(o[2*np+1], pl, vh[cur]+2);
            }
        }
    }

    {
        const int b_ = bh / NHEADS;
        const int h_ = bh % NHEADS;
        const float i0 = 1.0f / l0, i1 = 1.0f / l1;
        const int r0 = q0 + wid*16 + g;
        const int r1 = r0 + 8;
        const size_t base0 = ((size_t)(b_*SEQ + r0)) * D_MODEL + h_*HDIM;
        const size_t base1 = ((size_t)(b_*SEQ + r1)) * D_MODEL + h_*HDIM;
        #pragma unroll
        for (int ni = 0; ni < 8; ni++) {
            const int col = ni*8 + t*2;
            __nv_bfloat16 h0,l0b,h1,l1b;
            split2(o[ni][0]*i0, h0, l0b); split2(o[ni][1]*i0, h1, l1b);
            *reinterpret_cast<uint32_t*>(g_ah + base0 + col) = packbf(h0, h1);
            *reinterpret_cast<uint32_t*>(g_al + base0 + col) = packbf(l0b, l1b);
            split2(o[ni][2]*i1, h0, l0b); split2(o[ni][3]*i1, h1, l1b);
            *reinterpret_cast<uint32_t*>(g_ah + base1 + col) = packbf(h0, h1);
            *reinterpret_cast<uint32_t*>(g_al + base1 + col) = packbf(l0b, l1b);
        }
    }
}

// =====================================================================
extern "C" void kernel_launch(void* const* d_in, const int* in_sizes, int n_in,
                              void* d_out, int out_size)
{
    const float* query = (const float*)d_in[0];
    const float* key   = (const float*)d_in[1];
    const float* value = (const float*)d_in[2];
    const float* Wq    = (const float*)d_in[3];
    const float* bq    = (const float*)d_in[4];
    const float* Wk    = (const float*)d_in[5];
    const float* bk    = (const float*)d_in[6];
    const float* Wv    = (const float*)d_in[7];
    const float* bv    = (const float*)d_in[8];
    const float* Wo    = (const float*)d_in[9];
    const float* bo    = (const float*)d_in[10];
    float* out = (float*)d_out;

    cudaFuncSetAttribute(qkv_proj_kernel, cudaFuncAttributeMaxDynamicSharedMemorySize, GEMM_SMEM);
    cudaFuncSetAttribute(out_proj_kernel, cudaFuncAttributeMaxDynamicSharedMemorySize, GEMM_SMEM);
    cudaFuncSetAttribute(flash_attn_mma, cudaFuncAttributeMaxDynamicSharedMemorySize, ATTN_SMEM);

    split_all_kernel<<<SPLIT_BLOCKS, 256>>>(query, key, value, Wq, Wk, Wv, Wo);

    dim3 qkv_grid(D_MODEL/128, MTOT/128, 3);   // (8, 32, 3)
    qkv_proj_kernel<<<qkv_grid, 256, GEMM_SMEM>>>(bq, bk, bv);

    dim3 attn_grid(SEQ/128, BATCH*NHEADS);     // (16, 32)
    flash_attn_mma<<<attn_grid, 256, ATTN_SMEM>>>();

    dim3 oproj_grid(D_MODEL/128, MTOT/128);    // (8, 32)
    out_proj_kernel<<<oproj_grid, 256, GEMM_SMEM>>>(bo, out);
}